// round 5
// baseline (speedup 1.0000x reference)
#include <cuda_runtime.h>

#define BSZ 512
#define DIM 65536
#define NT 512
#define TILE 16384
#define SMEM_BYTES (TILE * 8)

struct Gate { short type; unsigned short m0; unsigned short m1; short ang; };
// type: 0=RX, 1=RY, 2=CNOT(m0=target mask, m1=control mask); ang indexes g_trig.

__device__ float2 g_psi[(long long)BSZ * DIM];   // 256 MB scratch statevector
__device__ float  g_norminv[BSZ];
__device__ float2 g_trig[24];                    // (cos(a/2), sin(a/2))
__device__ float  g_part[BSZ * 4 * 32];          // per-chunk measurement partials

// ---- Gate schedule (commutation-verified reordering of the reference circuit) ----
// Tile A local mask for wire w (w=2..15): 1<<(15-w).
// Tile B local mask: w in {6..15}: 1<<(15-w); w in {0..3}: 1<<(13-w).

__constant__ Gate cP1[17] = { // Tile A: random layer except gates on wires 0,1
  {1,1024,0,1},{2,16,32,0},{0,1,0,3},{1,2048,0,4},{2,32,64,0},{0,2,0,6},
  {1,4096,0,7},{2,64,128,0},{0,4,0,9},{1,8192,0,10},{2,128,256,0},{0,8,0,12},
  {2,256,512,0},{0,16,0,15},{2,512,1024,0},{0,32,0,18},{1,1,0,19}
};
__constant__ Gate cP2[20] = { // Tile B: deferred RX0/RY1/RY0, blk0 RX layer (no w4,w5), CNOT 0-1,1-2,2-3
  {0,8192,0,0},{1,4096,0,13},{1,8192,0,16},
  {0,8192,0,20},{0,4096,0,20},{0,2048,0,20},{0,1024,0,20},
  {0,512,0,20},{0,256,0,20},{0,128,0,20},{0,64,0,20},{0,32,0,20},{0,16,0,20},
  {0,8,0,20},{0,4,0,20},{0,2,0,20},{0,1,0,20},
  {2,4096,8192,0},{2,2048,4096,0},{2,1024,2048,0}
};
__constant__ Gate cP3[27] = { // Tile A: blk0 RX w4,w5, CNOT 3-4..14-15, blk0 RY w2..w14
  {0,2048,0,20},{0,1024,0,20},
  {2,2048,4096,0},{2,1024,2048,0},{2,512,1024,0},{2,256,512,0},{2,128,256,0},{2,64,128,0},
  {2,32,64,0},{2,16,32,0},{2,8,16,0},{2,4,8,0},{2,2,4,0},{2,1,2,0},
  {1,8192,0,22},{1,4096,0,22},{1,2048,0,22},{1,1024,0,22},{1,512,0,22},{1,256,0,22},
  {1,128,0,22},{1,64,0,22},{1,32,0,22},{1,16,0,22},{1,8,0,22},{1,4,0,22},{1,2,0,22}
};
__constant__ Gate cP4[21] = { // Tile B: CNOT 15-0, blk0 RY w15,w0,w1, blk1 RX layer (no w4,w5), CNOT 0-1,1-2,2-3
  {2,8192,1,0},{1,1,0,22},{1,8192,0,22},{1,4096,0,22},
  {0,8192,0,21},{0,4096,0,21},{0,2048,0,21},{0,1024,0,21},
  {0,512,0,21},{0,256,0,21},{0,128,0,21},{0,64,0,21},{0,32,0,21},{0,16,0,21},
  {0,8,0,21},{0,4,0,21},{0,2,0,21},{0,1,0,21},
  {2,4096,8192,0},{2,2048,4096,0},{2,1024,2048,0}
};
__constant__ Gate cP5[14] = { // Tile A: blk1 RX w4,w5, CNOT 3-4..14-15
  {0,2048,0,21},{0,1024,0,21},
  {2,2048,4096,0},{2,1024,2048,0},{2,512,1024,0},{2,256,512,0},{2,128,256,0},{2,64,128,0},
  {2,32,64,0},{2,16,32,0},{2,8,16,0},{2,4,8,0},{2,2,4,0},{2,1,2,0}
};
// Remaining ops (CNOT 15->0, blk1 RY layer, both measurements) are folded into the
// measurement operators: attn_0 = <Z15 Z0>, attn_w = <Z_w>;
// m_w = cos(th)*attn_w - sin(th)*<Xop_w> with Xop_0 = X_{w0}, Xop_15 = X15*X0, else X_w.

__device__ __forceinline__ void apply_gates(float2* t, const Gate* gs, int n) {
  for (int g = 0; g < n; ++g) {
    __syncthreads();
    const int type = gs[g].type;
    const int m0 = gs[g].m0;
    if (type == 2) {
      const int mC = gs[g].m1;
      const int lo = (m0 < mC) ? m0 : mC;
      const int hi = m0 ^ mC ^ lo;
      for (int q = threadIdx.x; q < TILE / 4; q += NT) {
        int i = ((q & ~(lo - 1)) << 1) | (q & (lo - 1));
        i = ((i & ~(hi - 1)) << 1) | (i & (hi - 1));
        i |= mC;                 // control = 1, target = 0
        float2 a = t[i];
        float2 b = t[i | m0];
        t[i] = b;
        t[i | m0] = a;
      }
    } else {
      const float2 cs = g_trig[gs[g].ang];
      const float c = cs.x, s = cs.y;
      if (m0 == 1) {             // adjacent pair: vectorized float4 path
        float4* t4 = (float4*)t;
        for (int q = threadIdx.x; q < TILE / 2; q += NT) {
          float4 v = t4[q];
          float4 r;
          if (type == 0) {       // RX
            r.x = c * v.x + s * v.w;   r.y = c * v.y - s * v.z;
            r.z = s * v.y + c * v.z;   r.w = -s * v.x + c * v.w;
          } else {               // RY
            r.x = c * v.x - s * v.z;   r.y = c * v.y - s * v.w;
            r.z = s * v.x + c * v.z;   r.w = s * v.y + c * v.w;
          }
          t4[q] = r;
        }
      } else {
        for (int q = threadIdx.x; q < TILE / 2; q += NT) {
          int i0 = ((q & ~(m0 - 1)) << 1) | (q & (m0 - 1));
          int i1 = i0 | m0;
          float2 a = t[i0], b = t[i1];
          float2 r0, r1;
          if (type == 0) {       // RX: a0' = c a0 - i s a1 ; a1' = -i s a0 + c a1
            r0.x = c * a.x + s * b.y;   r0.y = c * a.y - s * b.x;
            r1.x = s * a.y + c * b.x;   r1.y = -s * a.x + c * b.y;
          } else {               // RY
            r0.x = c * a.x - s * b.x;   r0.y = c * a.y - s * b.y;
            r1.x = s * a.x + c * b.x;   r1.y = s * a.y + c * b.y;
          }
          t[i0] = r0; t[i1] = r1;
        }
      }
    }
  }
  __syncthreads();
}

// ---- tile load/store ----
__device__ __forceinline__ void loadA(float2* t, int b, int o) {
  const float4* gp = (const float4*)(g_psi + (long long)b * DIM + o * TILE);
  float4* sp = (float4*)t;
  for (int k = threadIdx.x; k < TILE / 2; k += NT) sp[k] = gp[k];
}
__device__ __forceinline__ void storeA(const float2* t, int b, int o) {
  float4* gp = (float4*)(g_psi + (long long)b * DIM + o * TILE);
  const float4* sp = (const float4*)t;
  for (int k = threadIdx.x; k < TILE / 2; k += NT) gp[k] = sp[k];
}
// Tile B: local l bits [13:10] -> global bits [15:12]; l[9:0] -> global [9:0]; o -> bits [11:10]
__device__ __forceinline__ void loadB(float2* t, int b, int o) {
  const float2* base = g_psi + (long long)b * DIM + (o << 10);
  float4* sp = (float4*)t;
  for (int k = threadIdx.x; k < TILE / 2; k += NT) {
    int l = k << 1;
    int r = l >> 10, lo = l & 1023;
    sp[k] = *(const float4*)(base + ((long long)r << 12) + lo);
  }
}
__device__ __forceinline__ void storeB(const float2* t, int b, int o) {
  float2* base = g_psi + (long long)b * DIM + (o << 10);
  const float4* sp = (const float4*)t;
  for (int k = threadIdx.x; k < TILE / 2; k += NT) {
    int l = k << 1;
    int r = l >> 10, lo = l & 1023;
    *(float4*)(base + ((long long)r << 12) + lo) = sp[k];
  }
}

// ---- kernels ----
__global__ void kTrig(const float* ra, const float* trx, const float* try_) {
  int i = threadIdx.x;
  float a;
  if (i < 20) a = ra[i];
  else if (i < 22) a = trx[i - 20];
  else if (i < 24) a = try_[i - 22];
  else return;
  g_trig[i] = make_float2(cosf(a * 0.5f), sinf(a * 0.5f));
}

__global__ void __launch_bounds__(256) kNorm(const float* states) {
  __shared__ float red[256];
  int b = blockIdx.x;
  const float4* p = (const float4*)(states + (long long)b * DIM);
  float s = 0.f;
  for (int k = threadIdx.x; k < DIM / 4; k += 256) {
    float4 v = p[k];
    s += v.x * v.x + v.y * v.y + v.z * v.z + v.w * v.w;
  }
  red[threadIdx.x] = s;
  __syncthreads();
  for (int off = 128; off; off >>= 1) {
    if (threadIdx.x < off) red[threadIdx.x] += red[threadIdx.x + off];
    __syncthreads();
  }
  if (threadIdx.x == 0) g_norminv[b] = rsqrtf(red[0]);
}

__global__ void __launch_bounds__(NT) kP1(const float* states) {
  extern __shared__ float2 t[];
  int b = blockIdx.x >> 2, o = blockIdx.x & 3;
  float ninv = g_norminv[b];
  const float4* gp = (const float4*)(states + (long long)b * DIM + o * TILE);
  for (int k = threadIdx.x; k < TILE / 4; k += NT) {
    float4 v = gp[k];
    t[4 * k + 0] = make_float2(v.x * ninv, 0.f);
    t[4 * k + 1] = make_float2(v.y * ninv, 0.f);
    t[4 * k + 2] = make_float2(v.z * ninv, 0.f);
    t[4 * k + 3] = make_float2(v.w * ninv, 0.f);
  }
  apply_gates(t, cP1, 17);
  storeA(t, b, o);
}
__global__ void __launch_bounds__(NT) kP2() {
  extern __shared__ float2 t[];
  int b = blockIdx.x >> 2, o = blockIdx.x & 3;
  loadB(t, b, o); apply_gates(t, cP2, 20); storeB(t, b, o);
}
__global__ void __launch_bounds__(NT) kP3() {
  extern __shared__ float2 t[];
  int b = blockIdx.x >> 2, o = blockIdx.x & 3;
  loadA(t, b, o); apply_gates(t, cP3, 27); storeA(t, b, o);
}
__global__ void __launch_bounds__(NT) kP4() {
  extern __shared__ float2 t[];
  int b = blockIdx.x >> 2, o = blockIdx.x & 3;
  loadB(t, b, o); apply_gates(t, cP4, 21); storeB(t, b, o);
}
__global__ void __launch_bounds__(NT) kP5() {
  extern __shared__ float2 t[];
  int b = blockIdx.x >> 2, o = blockIdx.x & 3;
  loadA(t, b, o); apply_gates(t, cP5, 14); storeA(t, b, o);
}

__global__ void __launch_bounds__(NT) kMeasure() {
  extern __shared__ float2 t[];
  int b = blockIdx.x >> 2, o = blockIdx.x & 3;
  loadA(t, b, o);
  __syncthreads();

  float zacc[16], xacc[16];
#pragma unroll
  for (int w = 0; w < 16; ++w) { zacc[w] = 0.f; xacc[w] = 0.f; }

  // Diagonal ops: zacc[0] = <Z15 Z0> (bits 15 and 0), zacc[w] = <Z_w> (bit 15-w)
  for (int l = threadIdx.x; l < TILE; l += NT) {
    float2 a = t[l];
    float p = a.x * a.x + a.y * a.y;
    int i = (o << 14) | l;
    zacc[0] += (((i >> 15) ^ i) & 1) ? -p : p;
#pragma unroll
    for (int w = 1; w < 16; ++w)
      zacc[w] += ((i >> (15 - w)) & 1) ? -p : p;
  }

  // In-tile X ops: w = 2..14, mask = 1<<(15-w) (all within contiguous 16K chunk)
#pragma unroll
  for (int w = 2; w <= 14; ++w) {
    const int m = 1 << (15 - w);
    float acc = 0.f;
    for (int q = threadIdx.x; q < TILE / 2; q += NT) {
      int i0 = ((q & ~(m - 1)) << 1) | (q & (m - 1));
      float2 a = t[i0], bb = t[i0 | m];
      acc += a.x * bb.x + a.y * bb.y;
    }
    xacc[w] = 2.f * acc;
  }

  // Cross-tile X ops via global partner loads
  const float2* base = g_psi + (long long)b * DIM;
  if (o < 2) {  // bit15 == 0 for all elements: X_{w0} (mask 0x8000) and X15X0 (0x8001)
    float a0 = 0.f, a15 = 0.f;
    for (int l = threadIdx.x; l < TILE; l += NT) {
      int i = (o << 14) | l;
      float2 a = t[l];
      float2 p0 = base[i | 0x8000];
      float2 p1 = base[(i | 0x8000) ^ 1];
      a0 += a.x * p0.x + a.y * p0.y;
      a15 += a.x * p1.x + a.y * p1.y;
    }
    xacc[0] = 2.f * a0;
    xacc[15] = 2.f * a15;
  }
  if ((o & 1) == 0) {  // bit14 == 0: X_{w1} (mask 0x4000)
    float a1 = 0.f;
    for (int l = threadIdx.x; l < TILE; l += NT) {
      int i = (o << 14) | l;
      float2 a = t[l];
      float2 p = base[i | 0x4000];
      a1 += a.x * p.x + a.y * p.y;
    }
    xacc[1] = 2.f * a1;
  }

  // Block reduce 32 values
  __syncthreads();
  float* red = (float*)t;
  int lane = threadIdx.x & 31, wid = threadIdx.x >> 5;
#pragma unroll
  for (int v = 0; v < 32; ++v) {
    float val = (v < 16) ? zacc[v] : xacc[v - 16];
#pragma unroll
    for (int off = 16; off; off >>= 1) val += __shfl_down_sync(0xffffffffu, val, off);
    if (lane == 0) red[wid * 32 + v] = val;
  }
  __syncthreads();
  if (threadIdx.x < 32) {
    int v = threadIdx.x;
    float s = 0.f;
    for (int w = 0; w < NT / 32; ++w) s += red[w * 32 + v];
    g_part[blockIdx.x * 32 + v] = s;
  }
}

__global__ void __launch_bounds__(128) kHead(
    const float* theta_ry, const float* w1, const float* b1,
    const float* w2, const float* b2, const float* g1, const float* be1,
    const float* g2, const float* be2, const float* wh, const float* bh,
    float* out) {
  int b = blockIdx.x * blockDim.x + threadIdx.x;
  if (b >= BSZ) return;

  float attn[16], xs[16];
#pragma unroll
  for (int w = 0; w < 16; ++w) {
    float za = 0.f, xa = 0.f;
#pragma unroll
    for (int o = 0; o < 4; ++o) {
      za += g_part[(b * 4 + o) * 32 + w];
      xa += g_part[(b * 4 + o) * 32 + 16 + w];
    }
    attn[w] = za; xs[w] = xa;
  }
  float th = theta_ry[1];
  float cb = cosf(th), sb = sinf(th);
  float m[16];
#pragma unroll
  for (int w = 0; w < 16; ++w) m[w] = cb * attn[w] - sb * xs[w];

  // x = LN(attn) * g1[1] + be1[1]
  float mu = 0.f;
#pragma unroll
  for (int w = 0; w < 16; ++w) mu += attn[w];
  mu *= (1.f / 16.f);
  float var = 0.f;
#pragma unroll
  for (int w = 0; w < 16; ++w) { float d = attn[w] - mu; var += d * d; }
  var *= (1.f / 16.f);
  float rs = rsqrtf(var + 1e-5f);
  float x[16];
#pragma unroll
  for (int w = 0; w < 16; ++w) x[w] = (attn[w] - mu) * rs * g1[16 + w] + be1[16 + w];

  // ffn = relu(m @ W1^T + b1) @ W2^T + b2   (block 1 weights)
  float ffn[16];
#pragma unroll
  for (int w = 0; w < 16; ++w) ffn[w] = b2[16 + w];
  for (int j = 0; j < 64; ++j) {
    float h = b1[64 + j];
#pragma unroll
    for (int w = 0; w < 16; ++w) h += m[w] * w1[1024 + j * 16 + w];
    h = fmaxf(h, 0.f);
#pragma unroll
    for (int w = 0; w < 16; ++w) ffn[w] += h * w2[1024 + w * 64 + j];
  }

  // feats = LN(x + ffn) * g2[1] + be2[1]
  float y[16];
#pragma unroll
  for (int w = 0; w < 16; ++w) y[w] = x[w] + ffn[w];
  float mu2 = 0.f;
#pragma unroll
  for (int w = 0; w < 16; ++w) mu2 += y[w];
  mu2 *= (1.f / 16.f);
  float var2 = 0.f;
#pragma unroll
  for (int w = 0; w < 16; ++w) { float d = y[w] - mu2; var2 += d * d; }
  var2 *= (1.f / 16.f);
  float rs2 = rsqrtf(var2 + 1e-5f);

  float ov = bh[0];
#pragma unroll
  for (int w = 0; w < 16; ++w)
    ov += ((y[w] - mu2) * rs2 * g2[16 + w] + be2[16 + w]) * wh[w];
  out[b] = ov;
}

extern "C" void kernel_launch(void* const* d_in, const int* in_sizes, int n_in,
                              void* d_out, int out_size) {
  const float* states = (const float*)d_in[0];
  const float* ra     = (const float*)d_in[1];
  const float* trx    = (const float*)d_in[2];
  const float* try_   = (const float*)d_in[3];
  const float* w1     = (const float*)d_in[4];
  const float* b1     = (const float*)d_in[5];
  const float* w2     = (const float*)d_in[6];
  const float* b2     = (const float*)d_in[7];
  const float* g1     = (const float*)d_in[8];
  const float* be1    = (const float*)d_in[9];
  const float* g2     = (const float*)d_in[10];
  const float* be2    = (const float*)d_in[11];
  const float* wh     = (const float*)d_in[12];
  const float* bh     = (const float*)d_in[13];
  float* out = (float*)d_out;

  cudaFuncSetAttribute(kP1, cudaFuncAttributeMaxDynamicSharedMemorySize, SMEM_BYTES);
  cudaFuncSetAttribute(kP2, cudaFuncAttributeMaxDynamicSharedMemorySize, SMEM_BYTES);
  cudaFuncSetAttribute(kP3, cudaFuncAttributeMaxDynamicSharedMemorySize, SMEM_BYTES);
  cudaFuncSetAttribute(kP4, cudaFuncAttributeMaxDynamicSharedMemorySize, SMEM_BYTES);
  cudaFuncSetAttribute(kP5, cudaFuncAttributeMaxDynamicSharedMemorySize, SMEM_BYTES);
  cudaFuncSetAttribute(kMeasure, cudaFuncAttributeMaxDynamicSharedMemorySize, SMEM_BYTES);

  kTrig<<<1, 32>>>(ra, trx, try_);
  kNorm<<<BSZ, 256>>>(states);
  kP1<<<BSZ * 4, NT, SMEM_BYTES>>>(states);
  kP2<<<BSZ * 4, NT, SMEM_BYTES>>>();
  kP3<<<BSZ * 4, NT, SMEM_BYTES>>>();
  kP4<<<BSZ * 4, NT, SMEM_BYTES>>>();
  kP5<<<BSZ * 4, NT, SMEM_BYTES>>>();
  kMeasure<<<BSZ * 4, NT, SMEM_BYTES>>>();
  kHead<<<(BSZ + 127) / 128, 128>>>(try_, w1, b1, w2, b2, g1, be1, g2, be2, wh, bh, out);
}

// round 6
// speedup vs baseline: 1.0083x; 1.0083x over previous
#include <cuda_runtime.h>

#define BSZ 512
#define DIM 65536
#define NT 512
#define TILE 16384
#define SMEM_BYTES (TILE * 8)

struct Gate { short type; unsigned short m0; unsigned short m1; short ang; };
// type: 0=RX, 1=RY, 2=CNOT(m0=target mask, m1=control mask); ang indexes g_trig.

__device__ float2 g_psi[(long long)BSZ * DIM];   // 256 MB scratch statevector
__device__ float  g_norminv[BSZ];
__device__ float2 g_trig[24];                    // (cos(a/2), sin(a/2))
__device__ float  g_part[BSZ * 4 * 32];          // per-chunk measurement partials

// ---- Gate schedule (commutation-verified reordering of the reference circuit) ----
// Tile A local mask for wire w (w=2..15): 1<<(15-w).
// Tile B local mask: w in {6..15}: 1<<(15-w); w in {0..3}: 1<<(13-w).

__constant__ Gate cP1[17] = { // Tile A: random layer except gates on wires 0,1
  {1,1024,0,1},{2,16,32,0},{0,1,0,3},{1,2048,0,4},{2,32,64,0},{0,2,0,6},
  {1,4096,0,7},{2,64,128,0},{0,4,0,9},{1,8192,0,10},{2,128,256,0},{0,8,0,12},
  {2,256,512,0},{0,16,0,15},{2,512,1024,0},{0,32,0,18},{1,1,0,19}
};
__constant__ Gate cP2[20] = { // Tile B: deferred RX0/RY1/RY0, blk0 RX layer (no w4,w5), CNOT 0-1,1-2,2-3
  {0,8192,0,0},{1,4096,0,13},{1,8192,0,16},
  {0,8192,0,20},{0,4096,0,20},{0,2048,0,20},{0,1024,0,20},
  {0,512,0,20},{0,256,0,20},{0,128,0,20},{0,64,0,20},{0,32,0,20},{0,16,0,20},
  {0,8,0,20},{0,4,0,20},{0,2,0,20},{0,1,0,20},
  {2,4096,8192,0},{2,2048,4096,0},{2,1024,2048,0}
};
__constant__ Gate cP3[27] = { // Tile A: blk0 RX w4,w5, CNOT 3-4..14-15, blk0 RY w2..w14
  {0,2048,0,20},{0,1024,0,20},
  {2,2048,4096,0},{2,1024,2048,0},{2,512,1024,0},{2,256,512,0},{2,128,256,0},{2,64,128,0},
  {2,32,64,0},{2,16,32,0},{2,8,16,0},{2,4,8,0},{2,2,4,0},{2,1,2,0},
  {1,8192,0,22},{1,4096,0,22},{1,2048,0,22},{1,1024,0,22},{1,512,0,22},{1,256,0,22},
  {1,128,0,22},{1,64,0,22},{1,32,0,22},{1,16,0,22},{1,8,0,22},{1,4,0,22},{1,2,0,22}
};
__constant__ Gate cP4[21] = { // Tile B: CNOT 15-0, blk0 RY w15,w0,w1, blk1 RX layer (no w4,w5), CNOT 0-1,1-2,2-3
  {2,8192,1,0},{1,1,0,22},{1,8192,0,22},{1,4096,0,22},
  {0,8192,0,21},{0,4096,0,21},{0,2048,0,21},{0,1024,0,21},
  {0,512,0,21},{0,256,0,21},{0,128,0,21},{0,64,0,21},{0,32,0,21},{0,16,0,21},
  {0,8,0,21},{0,4,0,21},{0,2,0,21},{0,1,0,21},
  {2,4096,8192,0},{2,2048,4096,0},{2,1024,2048,0}
};
__constant__ Gate cP5[14] = { // Tile A: blk1 RX w4,w5, CNOT 3-4..14-15
  {0,2048,0,21},{0,1024,0,21},
  {2,2048,4096,0},{2,1024,2048,0},{2,512,1024,0},{2,256,512,0},{2,128,256,0},{2,64,128,0},
  {2,32,64,0},{2,16,32,0},{2,8,16,0},{2,4,8,0},{2,2,4,0},{2,1,2,0}
};
// Remaining ops (CNOT 15->0, blk1 RY layer, both measurements) are folded into the
// measurement operators: attn_0 = <Z15 Z0>, attn_w = <Z_w>;
// m_w = cos(th)*attn_w - sin(th)*<Xop_w> with Xop_0 = X_{w0}, Xop_15 = X15*X0, else X_w.

__device__ __forceinline__ void apply_gates(float2* t, const Gate* gs, int n) {
  for (int g = 0; g < n; ++g) {
    __syncthreads();
    const int type = gs[g].type;
    const int m0 = gs[g].m0;
    if (type == 2) {
      const int mC = gs[g].m1;
      const int lo = (m0 < mC) ? m0 : mC;
      const int hi = m0 ^ mC ^ lo;
      for (int q = threadIdx.x; q < TILE / 4; q += NT) {
        int i = ((q & ~(lo - 1)) << 1) | (q & (lo - 1));
        i = ((i & ~(hi - 1)) << 1) | (i & (hi - 1));
        i |= mC;                 // control = 1, target = 0
        float2 a = t[i];
        float2 b = t[i | m0];
        t[i] = b;
        t[i | m0] = a;
      }
    } else {
      const float2 cs = g_trig[gs[g].ang];
      const float c = cs.x, s = cs.y;
      if (m0 == 1) {             // adjacent pair: vectorized float4 path
        float4* t4 = (float4*)t;
        for (int q = threadIdx.x; q < TILE / 2; q += NT) {
          float4 v = t4[q];
          float4 r;
          if (type == 0) {       // RX
            r.x = c * v.x + s * v.w;   r.y = c * v.y - s * v.z;
            r.z = s * v.y + c * v.z;   r.w = -s * v.x + c * v.w;
          } else {               // RY
            r.x = c * v.x - s * v.z;   r.y = c * v.y - s * v.w;
            r.z = s * v.x + c * v.z;   r.w = s * v.y + c * v.w;
          }
          t4[q] = r;
        }
      } else {
        for (int q = threadIdx.x; q < TILE / 2; q += NT) {
          int i0 = ((q & ~(m0 - 1)) << 1) | (q & (m0 - 1));
          int i1 = i0 | m0;
          float2 a = t[i0], b = t[i1];
          float2 r0, r1;
          if (type == 0) {       // RX: a0' = c a0 - i s a1 ; a1' = -i s a0 + c a1
            r0.x = c * a.x + s * b.y;   r0.y = c * a.y - s * b.x;
            r1.x = s * a.y + c * b.x;   r1.y = -s * a.x + c * b.y;
          } else {               // RY
            r0.x = c * a.x - s * b.x;   r0.y = c * a.y - s * b.y;
            r1.x = s * a.x + c * b.x;   r1.y = s * a.y + c * b.y;
          }
          t[i0] = r0; t[i1] = r1;
        }
      }
    }
  }
  __syncthreads();
}

// ---- tile load/store ----
__device__ __forceinline__ void loadA(float2* t, int b, int o) {
  const float4* gp = (const float4*)(g_psi + (long long)b * DIM + o * TILE);
  float4* sp = (float4*)t;
  for (int k = threadIdx.x; k < TILE / 2; k += NT) sp[k] = gp[k];
}
__device__ __forceinline__ void storeA(const float2* t, int b, int o) {
  float4* gp = (float4*)(g_psi + (long long)b * DIM + o * TILE);
  const float4* sp = (const float4*)t;
  for (int k = threadIdx.x; k < TILE / 2; k += NT) gp[k] = sp[k];
}
// Tile B: local l bits [13:10] -> global bits [15:12]; l[9:0] -> global [9:0]; o -> bits [11:10]
__device__ __forceinline__ void loadB(float2* t, int b, int o) {
  const float2* base = g_psi + (long long)b * DIM + (o << 10);
  float4* sp = (float4*)t;
  for (int k = threadIdx.x; k < TILE / 2; k += NT) {
    int l = k << 1;
    int r = l >> 10, lo = l & 1023;
    sp[k] = *(const float4*)(base + ((long long)r << 12) + lo);
  }
}
__device__ __forceinline__ void storeB(const float2* t, int b, int o) {
  float2* base = g_psi + (long long)b * DIM + (o << 10);
  const float4* sp = (const float4*)t;
  for (int k = threadIdx.x; k < TILE / 2; k += NT) {
    int l = k << 1;
    int r = l >> 10, lo = l & 1023;
    *(float4*)(base + ((long long)r << 12) + lo) = sp[k];
  }
}

// ---- kernels ----
__global__ void kTrig(const float* ra, const float* trx, const float* try_) {
  int i = threadIdx.x;
  float a;
  if (i < 20) a = ra[i];
  else if (i < 22) a = trx[i - 20];
  else if (i < 24) a = try_[i - 22];
  else return;
  g_trig[i] = make_float2(cosf(a * 0.5f), sinf(a * 0.5f));
}

__global__ void __launch_bounds__(256) kNorm(const float* states) {
  __shared__ float red[256];
  int b = blockIdx.x;
  const float4* p = (const float4*)(states + (long long)b * DIM);
  float s = 0.f;
  for (int k = threadIdx.x; k < DIM / 4; k += 256) {
    float4 v = p[k];
    s += v.x * v.x + v.y * v.y + v.z * v.z + v.w * v.w;
  }
  red[threadIdx.x] = s;
  __syncthreads();
  for (int off = 128; off; off >>= 1) {
    if (threadIdx.x < off) red[threadIdx.x] += red[threadIdx.x + off];
    __syncthreads();
  }
  if (threadIdx.x == 0) g_norminv[b] = rsqrtf(red[0]);
}

__global__ void __launch_bounds__(NT) kP1(const float* states) {
  extern __shared__ float2 t[];
  int b = blockIdx.x >> 2, o = blockIdx.x & 3;
  float ninv = g_norminv[b];
  const float4* gp = (const float4*)(states + (long long)b * DIM + o * TILE);
  for (int k = threadIdx.x; k < TILE / 4; k += NT) {
    float4 v = gp[k];
    t[4 * k + 0] = make_float2(v.x * ninv, 0.f);
    t[4 * k + 1] = make_float2(v.y * ninv, 0.f);
    t[4 * k + 2] = make_float2(v.z * ninv, 0.f);
    t[4 * k + 3] = make_float2(v.w * ninv, 0.f);
  }
  apply_gates(t, cP1, 17);
  storeA(t, b, o);
}
__global__ void __launch_bounds__(NT) kP2() {
  extern __shared__ float2 t[];
  int b = blockIdx.x >> 2, o = blockIdx.x & 3;
  loadB(t, b, o); apply_gates(t, cP2, 20); storeB(t, b, o);
}
__global__ void __launch_bounds__(NT) kP3() {
  extern __shared__ float2 t[];
  int b = blockIdx.x >> 2, o = blockIdx.x & 3;
  loadA(t, b, o); apply_gates(t, cP3, 27); storeA(t, b, o);
}
__global__ void __launch_bounds__(NT) kP4() {
  extern __shared__ float2 t[];
  int b = blockIdx.x >> 2, o = blockIdx.x & 3;
  loadB(t, b, o); apply_gates(t, cP4, 21); storeB(t, b, o);
}
__global__ void __launch_bounds__(NT) kP5() {
  extern __shared__ float2 t[];
  int b = blockIdx.x >> 2, o = blockIdx.x & 3;
  loadA(t, b, o); apply_gates(t, cP5, 14); storeA(t, b, o);
}

__global__ void __launch_bounds__(NT) kMeasure() {
  extern __shared__ float2 t[];
  int b = blockIdx.x >> 2, o = blockIdx.x & 3;
  loadA(t, b, o);
  __syncthreads();

  float zacc[16], xacc[16];
#pragma unroll
  for (int w = 0; w < 16; ++w) { zacc[w] = 0.f; xacc[w] = 0.f; }

  // Diagonal ops: zacc[0] = <Z15 Z0> (bits 15 and 0), zacc[w] = <Z_w> (bit 15-w)
  for (int l = threadIdx.x; l < TILE; l += NT) {
    float2 a = t[l];
    float p = a.x * a.x + a.y * a.y;
    int i = (o << 14) | l;
    zacc[0] += (((i >> 15) ^ i) & 1) ? -p : p;
#pragma unroll
    for (int w = 1; w < 16; ++w)
      zacc[w] += ((i >> (15 - w)) & 1) ? -p : p;
  }

  // In-tile X ops: w = 2..14, mask = 1<<(15-w) (all within contiguous 16K chunk)
#pragma unroll
  for (int w = 2; w <= 14; ++w) {
    const int m = 1 << (15 - w);
    float acc = 0.f;
    for (int q = threadIdx.x; q < TILE / 2; q += NT) {
      int i0 = ((q & ~(m - 1)) << 1) | (q & (m - 1));
      float2 a = t[i0], bb = t[i0 | m];
      acc += a.x * bb.x + a.y * bb.y;
    }
    xacc[w] = 2.f * acc;
  }

  // Cross-tile X ops via global partner loads
  const float2* base = g_psi + (long long)b * DIM;
  if (o < 2) {  // bit15 == 0 for all elements: X_{w0} (mask 0x8000) and X15X0 (0x8001)
    float a0 = 0.f, a15 = 0.f;
    for (int l = threadIdx.x; l < TILE; l += NT) {
      int i = (o << 14) | l;
      float2 a = t[l];
      float2 p0 = base[i | 0x8000];
      float2 p1 = base[(i | 0x8000) ^ 1];
      a0 += a.x * p0.x + a.y * p0.y;
      a15 += a.x * p1.x + a.y * p1.y;
    }
    xacc[0] = 2.f * a0;
    xacc[15] = 2.f * a15;
  }
  if ((o & 1) == 0) {  // bit14 == 0: X_{w1} (mask 0x4000)
    float a1 = 0.f;
    for (int l = threadIdx.x; l < TILE; l += NT) {
      int i = (o << 14) | l;
      float2 a = t[l];
      float2 p = base[i | 0x4000];
      a1 += a.x * p.x + a.y * p.y;
    }
    xacc[1] = 2.f * a1;
  }

  // Block reduce 32 values
  __syncthreads();
  float* red = (float*)t;
  int lane = threadIdx.x & 31, wid = threadIdx.x >> 5;
#pragma unroll
  for (int v = 0; v < 32; ++v) {
    float val = (v < 16) ? zacc[v] : xacc[v - 16];
#pragma unroll
    for (int off = 16; off; off >>= 1) val += __shfl_down_sync(0xffffffffu, val, off);
    if (lane == 0) red[wid * 32 + v] = val;
  }
  __syncthreads();
  if (threadIdx.x < 32) {
    int v = threadIdx.x;
    float s = 0.f;
    for (int w = 0; w < NT / 32; ++w) s += red[w * 32 + v];
    g_part[blockIdx.x * 32 + v] = s;
  }
}

__global__ void __launch_bounds__(128) kHead(
    const float* theta_ry, const float* w1, const float* b1,
    const float* w2, const float* b2, const float* g1, const float* be1,
    const float* g2, const float* be2, const float* wh, const float* bh,
    float* out) {
  int b = blockIdx.x * blockDim.x + threadIdx.x;
  if (b >= BSZ) return;

  float attn[16], xs[16];
#pragma unroll
  for (int w = 0; w < 16; ++w) {
    float za = 0.f, xa = 0.f;
#pragma unroll
    for (int o = 0; o < 4; ++o) {
      za += g_part[(b * 4 + o) * 32 + w];
      xa += g_part[(b * 4 + o) * 32 + 16 + w];
    }
    attn[w] = za; xs[w] = xa;
  }
  float th = theta_ry[1];
  float cb = cosf(th), sb = sinf(th);
  float m[16];
#pragma unroll
  for (int w = 0; w < 16; ++w) m[w] = cb * attn[w] - sb * xs[w];

  // x = LN(attn) * g1[1] + be1[1]
  float mu = 0.f;
#pragma unroll
  for (int w = 0; w < 16; ++w) mu += attn[w];
  mu *= (1.f / 16.f);
  float var = 0.f;
#pragma unroll
  for (int w = 0; w < 16; ++w) { float d = attn[w] - mu; var += d * d; }
  var *= (1.f / 16.f);
  float rs = rsqrtf(var + 1e-5f);
  float x[16];
#pragma unroll
  for (int w = 0; w < 16; ++w) x[w] = (attn[w] - mu) * rs * g1[16 + w] + be1[16 + w];

  // ffn = relu(m @ W1^T + b1) @ W2^T + b2   (block 1 weights)
  float ffn[16];
#pragma unroll
  for (int w = 0; w < 16; ++w) ffn[w] = b2[16 + w];
  for (int j = 0; j < 64; ++j) {
    float h = b1[64 + j];
#pragma unroll
    for (int w = 0; w < 16; ++w) h += m[w] * w1[1024 + j * 16 + w];
    h = fmaxf(h, 0.f);
#pragma unroll
    for (int w = 0; w < 16; ++w) ffn[w] += h * w2[1024 + w * 64 + j];
  }

  // feats = LN(x + ffn) * g2[1] + be2[1]
  float y[16];
#pragma unroll
  for (int w = 0; w < 16; ++w) y[w] = x[w] + ffn[w];
  float mu2 = 0.f;
#pragma unroll
  for (int w = 0; w < 16; ++w) mu2 += y[w];
  mu2 *= (1.f / 16.f);
  float var2 = 0.f;
#pragma unroll
  for (int w = 0; w < 16; ++w) { float d = y[w] - mu2; var2 += d * d; }
  var2 *= (1.f / 16.f);
  float rs2 = rsqrtf(var2 + 1e-5f);

  float ov = bh[0];
#pragma unroll
  for (int w = 0; w < 16; ++w)
    ov += ((y[w] - mu2) * rs2 * g2[16 + w] + be2[16 + w]) * wh[w];
  out[b] = ov;
}

extern "C" void kernel_launch(void* const* d_in, const int* in_sizes, int n_in,
                              void* d_out, int out_size) {
  const float* states = (const float*)d_in[0];
  const float* ra     = (const float*)d_in[1];
  const float* trx    = (const float*)d_in[2];
  const float* try_   = (const float*)d_in[3];
  const float* w1     = (const float*)d_in[4];
  const float* b1     = (const float*)d_in[5];
  const float* w2     = (const float*)d_in[6];
  const float* b2     = (const float*)d_in[7];
  const float* g1     = (const float*)d_in[8];
  const float* be1    = (const float*)d_in[9];
  const float* g2     = (const float*)d_in[10];
  const float* be2    = (const float*)d_in[11];
  const float* wh     = (const float*)d_in[12];
  const float* bh     = (const float*)d_in[13];
  float* out = (float*)d_out;

  cudaFuncSetAttribute(kP1, cudaFuncAttributeMaxDynamicSharedMemorySize, SMEM_BYTES);
  cudaFuncSetAttribute(kP2, cudaFuncAttributeMaxDynamicSharedMemorySize, SMEM_BYTES);
  cudaFuncSetAttribute(kP3, cudaFuncAttributeMaxDynamicSharedMemorySize, SMEM_BYTES);
  cudaFuncSetAttribute(kP4, cudaFuncAttributeMaxDynamicSharedMemorySize, SMEM_BYTES);
  cudaFuncSetAttribute(kP5, cudaFuncAttributeMaxDynamicSharedMemorySize, SMEM_BYTES);
  cudaFuncSetAttribute(kMeasure, cudaFuncAttributeMaxDynamicSharedMemorySize, SMEM_BYTES);

  kTrig<<<1, 32>>>(ra, trx, try_);
  kNorm<<<BSZ, 256>>>(states);
  kP1<<<BSZ * 4, NT, SMEM_BYTES>>>(states);
  kP2<<<BSZ * 4, NT, SMEM_BYTES>>>();
  kP3<<<BSZ * 4, NT, SMEM_BYTES>>>();
  kP4<<<BSZ * 4, NT, SMEM_BYTES>>>();
  kP5<<<BSZ * 4, NT, SMEM_BYTES>>>();
  kMeasure<<<BSZ * 4, NT, SMEM_BYTES>>>();
  kHead<<<(BSZ + 127) / 128, 128>>>(try_, w1, b1, w2, b2, g1, be1, g2, be2, wh, bh, out);
}

// round 7
// speedup vs baseline: 1.0093x; 1.0010x over previous
#include <cuda_runtime.h>

#define BSZ 512
#define DIM 65536
#define NT 512
#define TILE 16384
#define SMEM_BYTES (TILE * 8)

struct Gate { short type; unsigned short m0; unsigned short m1; short ang; };
// type: 0=RX, 1=RY, 2=CNOT(m0=target mask, m1=control mask); ang indexes g_trig.

__device__ float2 g_psi[(long long)BSZ * DIM];   // 256 MB scratch statevector
__device__ float  g_norminv[BSZ];
__device__ float2 g_trig[24];                    // (cos(a/2), sin(a/2))
__device__ float  g_part[BSZ * 4 * 32];          // per-chunk measurement partials

// ---- Gate schedule (commutation-verified reordering of the reference circuit) ----
// Tile A local mask for wire w (w=2..15): 1<<(15-w).
// Tile B local mask: w in {6..15}: 1<<(15-w); w in {0..3}: 1<<(13-w).

__constant__ Gate cP1[17] = { // Tile A: random layer except gates on wires 0,1
  {1,1024,0,1},{2,16,32,0},{0,1,0,3},{1,2048,0,4},{2,32,64,0},{0,2,0,6},
  {1,4096,0,7},{2,64,128,0},{0,4,0,9},{1,8192,0,10},{2,128,256,0},{0,8,0,12},
  {2,256,512,0},{0,16,0,15},{2,512,1024,0},{0,32,0,18},{1,1,0,19}
};
__constant__ Gate cP2[20] = { // Tile B: deferred RX0/RY1/RY0, blk0 RX layer (no w4,w5), CNOT 0-1,1-2,2-3
  {0,8192,0,0},{1,4096,0,13},{1,8192,0,16},
  {0,8192,0,20},{0,4096,0,20},{0,2048,0,20},{0,1024,0,20},
  {0,512,0,20},{0,256,0,20},{0,128,0,20},{0,64,0,20},{0,32,0,20},{0,16,0,20},
  {0,8,0,20},{0,4,0,20},{0,2,0,20},{0,1,0,20},
  {2,4096,8192,0},{2,2048,4096,0},{2,1024,2048,0}
};
__constant__ Gate cP3[27] = { // Tile A: blk0 RX w4,w5, CNOT 3-4..14-15, blk0 RY w2..w14
  {0,2048,0,20},{0,1024,0,20},
  {2,2048,4096,0},{2,1024,2048,0},{2,512,1024,0},{2,256,512,0},{2,128,256,0},{2,64,128,0},
  {2,32,64,0},{2,16,32,0},{2,8,16,0},{2,4,8,0},{2,2,4,0},{2,1,2,0},
  {1,8192,0,22},{1,4096,0,22},{1,2048,0,22},{1,1024,0,22},{1,512,0,22},{1,256,0,22},
  {1,128,0,22},{1,64,0,22},{1,32,0,22},{1,16,0,22},{1,8,0,22},{1,4,0,22},{1,2,0,22}
};
__constant__ Gate cP4[21] = { // Tile B: CNOT 15-0, blk0 RY w15,w0,w1, blk1 RX layer (no w4,w5), CNOT 0-1,1-2,2-3
  {2,8192,1,0},{1,1,0,22},{1,8192,0,22},{1,4096,0,22},
  {0,8192,0,21},{0,4096,0,21},{0,2048,0,21},{0,1024,0,21},
  {0,512,0,21},{0,256,0,21},{0,128,0,21},{0,64,0,21},{0,32,0,21},{0,16,0,21},
  {0,8,0,21},{0,4,0,21},{0,2,0,21},{0,1,0,21},
  {2,4096,8192,0},{2,2048,4096,0},{2,1024,2048,0}
};
__constant__ Gate cP5[14] = { // Tile A: blk1 RX w4,w5, CNOT 3-4..14-15
  {0,2048,0,21},{0,1024,0,21},
  {2,2048,4096,0},{2,1024,2048,0},{2,512,1024,0},{2,256,512,0},{2,128,256,0},{2,64,128,0},
  {2,32,64,0},{2,16,32,0},{2,8,16,0},{2,4,8,0},{2,2,4,0},{2,1,2,0}
};
// Remaining ops (CNOT 15->0, blk1 RY layer, both measurements) are folded into the
// measurement operators: attn_0 = <Z15 Z0>, attn_w = <Z_w>;
// m_w = cos(th)*attn_w - sin(th)*<Xop_w> with Xop_0 = X_{w0}, Xop_15 = X15*X0, else X_w.

__device__ __forceinline__ void apply_gates(float2* t, const Gate* gs, int n) {
  for (int g = 0; g < n; ++g) {
    __syncthreads();
    const int type = gs[g].type;
    const int m0 = gs[g].m0;
    if (type == 2) {
      const int mC = gs[g].m1;
      const int lo = (m0 < mC) ? m0 : mC;
      const int hi = m0 ^ mC ^ lo;
      for (int q = threadIdx.x; q < TILE / 4; q += NT) {
        int i = ((q & ~(lo - 1)) << 1) | (q & (lo - 1));
        i = ((i & ~(hi - 1)) << 1) | (i & (hi - 1));
        i |= mC;                 // control = 1, target = 0
        float2 a = t[i];
        float2 b = t[i | m0];
        t[i] = b;
        t[i | m0] = a;
      }
    } else {
      const float2 cs = g_trig[gs[g].ang];
      const float c = cs.x, s = cs.y;
      if (m0 == 1) {             // adjacent pair: vectorized float4 path
        float4* t4 = (float4*)t;
        for (int q = threadIdx.x; q < TILE / 2; q += NT) {
          float4 v = t4[q];
          float4 r;
          if (type == 0) {       // RX
            r.x = c * v.x + s * v.w;   r.y = c * v.y - s * v.z;
            r.z = s * v.y + c * v.z;   r.w = -s * v.x + c * v.w;
          } else {               // RY
            r.x = c * v.x - s * v.z;   r.y = c * v.y - s * v.w;
            r.z = s * v.x + c * v.z;   r.w = s * v.y + c * v.w;
          }
          t4[q] = r;
        }
      } else {
        for (int q = threadIdx.x; q < TILE / 2; q += NT) {
          int i0 = ((q & ~(m0 - 1)) << 1) | (q & (m0 - 1));
          int i1 = i0 | m0;
          float2 a = t[i0], b = t[i1];
          float2 r0, r1;
          if (type == 0) {       // RX: a0' = c a0 - i s a1 ; a1' = -i s a0 + c a1
            r0.x = c * a.x + s * b.y;   r0.y = c * a.y - s * b.x;
            r1.x = s * a.y + c * b.x;   r1.y = -s * a.x + c * b.y;
          } else {               // RY
            r0.x = c * a.x - s * b.x;   r0.y = c * a.y - s * b.y;
            r1.x = s * a.x + c * b.x;   r1.y = s * a.y + c * b.y;
          }
          t[i0] = r0; t[i1] = r1;
        }
      }
    }
  }
  __syncthreads();
}

// ---- tile load/store ----
__device__ __forceinline__ void loadA(float2* t, int b, int o) {
  const float4* gp = (const float4*)(g_psi + (long long)b * DIM + o * TILE);
  float4* sp = (float4*)t;
  for (int k = threadIdx.x; k < TILE / 2; k += NT) sp[k] = gp[k];
}
__device__ __forceinline__ void storeA(const float2* t, int b, int o) {
  float4* gp = (float4*)(g_psi + (long long)b * DIM + o * TILE);
  const float4* sp = (const float4*)t;
  for (int k = threadIdx.x; k < TILE / 2; k += NT) gp[k] = sp[k];
}
// Tile B: local l bits [13:10] -> global bits [15:12]; l[9:0] -> global [9:0]; o -> bits [11:10]
__device__ __forceinline__ void loadB(float2* t, int b, int o) {
  const float2* base = g_psi + (long long)b * DIM + (o << 10);
  float4* sp = (float4*)t;
  for (int k = threadIdx.x; k < TILE / 2; k += NT) {
    int l = k << 1;
    int r = l >> 10, lo = l & 1023;
    sp[k] = *(const float4*)(base + ((long long)r << 12) + lo);
  }
}
__device__ __forceinline__ void storeB(const float2* t, int b, int o) {
  float2* base = g_psi + (long long)b * DIM + (o << 10);
  const float4* sp = (const float4*)t;
  for (int k = threadIdx.x; k < TILE / 2; k += NT) {
    int l = k << 1;
    int r = l >> 10, lo = l & 1023;
    *(float4*)(base + ((long long)r << 12) + lo) = sp[k];
  }
}

// ---- kernels ----
__global__ void kTrig(const float* ra, const float* trx, const float* try_) {
  int i = threadIdx.x;
  float a;
  if (i < 20) a = ra[i];
  else if (i < 22) a = trx[i - 20];
  else if (i < 24) a = try_[i - 22];
  else return;
  g_trig[i] = make_float2(cosf(a * 0.5f), sinf(a * 0.5f));
}

__global__ void __launch_bounds__(256) kNorm(const float* states) {
  __shared__ float red[256];
  int b = blockIdx.x;
  const float4* p = (const float4*)(states + (long long)b * DIM);
  float s = 0.f;
  for (int k = threadIdx.x; k < DIM / 4; k += 256) {
    float4 v = p[k];
    s += v.x * v.x + v.y * v.y + v.z * v.z + v.w * v.w;
  }
  red[threadIdx.x] = s;
  __syncthreads();
  for (int off = 128; off; off >>= 1) {
    if (threadIdx.x < off) red[threadIdx.x] += red[threadIdx.x + off];
    __syncthreads();
  }
  if (threadIdx.x == 0) g_norminv[b] = rsqrtf(red[0]);
}

__global__ void __launch_bounds__(NT) kP1(const float* states) {
  extern __shared__ float2 t[];
  int b = blockIdx.x >> 2, o = blockIdx.x & 3;
  float ninv = g_norminv[b];
  const float4* gp = (const float4*)(states + (long long)b * DIM + o * TILE);
  for (int k = threadIdx.x; k < TILE / 4; k += NT) {
    float4 v = gp[k];
    t[4 * k + 0] = make_float2(v.x * ninv, 0.f);
    t[4 * k + 1] = make_float2(v.y * ninv, 0.f);
    t[4 * k + 2] = make_float2(v.z * ninv, 0.f);
    t[4 * k + 3] = make_float2(v.w * ninv, 0.f);
  }
  apply_gates(t, cP1, 17);
  storeA(t, b, o);
}
__global__ void __launch_bounds__(NT) kP2() {
  extern __shared__ float2 t[];
  int b = blockIdx.x >> 2, o = blockIdx.x & 3;
  loadB(t, b, o); apply_gates(t, cP2, 20); storeB(t, b, o);
}
__global__ void __launch_bounds__(NT) kP3() {
  extern __shared__ float2 t[];
  int b = blockIdx.x >> 2, o = blockIdx.x & 3;
  loadA(t, b, o); apply_gates(t, cP3, 27); storeA(t, b, o);
}
__global__ void __launch_bounds__(NT) kP4() {
  extern __shared__ float2 t[];
  int b = blockIdx.x >> 2, o = blockIdx.x & 3;
  loadB(t, b, o); apply_gates(t, cP4, 21); storeB(t, b, o);
}
__global__ void __launch_bounds__(NT) kP5() {
  extern __shared__ float2 t[];
  int b = blockIdx.x >> 2, o = blockIdx.x & 3;
  loadA(t, b, o); apply_gates(t, cP5, 14); storeA(t, b, o);
}

__global__ void __launch_bounds__(NT) kMeasure() {
  extern __shared__ float2 t[];
  int b = blockIdx.x >> 2, o = blockIdx.x & 3;
  loadA(t, b, o);
  __syncthreads();

  float zacc[16], xacc[16];
#pragma unroll
  for (int w = 0; w < 16; ++w) { zacc[w] = 0.f; xacc[w] = 0.f; }

  // Diagonal ops: zacc[0] = <Z15 Z0> (bits 15 and 0), zacc[w] = <Z_w> (bit 15-w)
  for (int l = threadIdx.x; l < TILE; l += NT) {
    float2 a = t[l];
    float p = a.x * a.x + a.y * a.y;
    int i = (o << 14) | l;
    zacc[0] += (((i >> 15) ^ i) & 1) ? -p : p;
#pragma unroll
    for (int w = 1; w < 16; ++w)
      zacc[w] += ((i >> (15 - w)) & 1) ? -p : p;
  }

  // In-tile X ops: w = 2..14, mask = 1<<(15-w) (all within contiguous 16K chunk)
#pragma unroll
  for (int w = 2; w <= 14; ++w) {
    const int m = 1 << (15 - w);
    float acc = 0.f;
    for (int q = threadIdx.x; q < TILE / 2; q += NT) {
      int i0 = ((q & ~(m - 1)) << 1) | (q & (m - 1));
      float2 a = t[i0], bb = t[i0 | m];
      acc += a.x * bb.x + a.y * bb.y;
    }
    xacc[w] = 2.f * acc;
  }

  // Cross-tile X ops via global partner loads
  const float2* base = g_psi + (long long)b * DIM;
  if (o < 2) {  // bit15 == 0 for all elements: X_{w0} (mask 0x8000) and X15X0 (0x8001)
    float a0 = 0.f, a15 = 0.f;
    for (int l = threadIdx.x; l < TILE; l += NT) {
      int i = (o << 14) | l;
      float2 a = t[l];
      float2 p0 = base[i | 0x8000];
      float2 p1 = base[(i | 0x8000) ^ 1];
      a0 += a.x * p0.x + a.y * p0.y;
      a15 += a.x * p1.x + a.y * p1.y;
    }
    xacc[0] = 2.f * a0;
    xacc[15] = 2.f * a15;
  }
  if ((o & 1) == 0) {  // bit14 == 0: X_{w1} (mask 0x4000)
    float a1 = 0.f;
    for (int l = threadIdx.x; l < TILE; l += NT) {
      int i = (o << 14) | l;
      float2 a = t[l];
      float2 p = base[i | 0x4000];
      a1 += a.x * p.x + a.y * p.y;
    }
    xacc[1] = 2.f * a1;
  }

  // Block reduce 32 values
  __syncthreads();
  float* red = (float*)t;
  int lane = threadIdx.x & 31, wid = threadIdx.x >> 5;
#pragma unroll
  for (int v = 0; v < 32; ++v) {
    float val = (v < 16) ? zacc[v] : xacc[v - 16];
#pragma unroll
    for (int off = 16; off; off >>= 1) val += __shfl_down_sync(0xffffffffu, val, off);
    if (lane == 0) red[wid * 32 + v] = val;
  }
  __syncthreads();
  if (threadIdx.x < 32) {
    int v = threadIdx.x;
    float s = 0.f;
    for (int w = 0; w < NT / 32; ++w) s += red[w * 32 + v];
    g_part[blockIdx.x * 32 + v] = s;
  }
}

__global__ void __launch_bounds__(128) kHead(
    const float* theta_ry, const float* w1, const float* b1,
    const float* w2, const float* b2, const float* g1, const float* be1,
    const float* g2, const float* be2, const float* wh, const float* bh,
    float* out) {
  int b = blockIdx.x * blockDim.x + threadIdx.x;
  if (b >= BSZ) return;

  float attn[16], xs[16];
#pragma unroll
  for (int w = 0; w < 16; ++w) {
    float za = 0.f, xa = 0.f;
#pragma unroll
    for (int o = 0; o < 4; ++o) {
      za += g_part[(b * 4 + o) * 32 + w];
      xa += g_part[(b * 4 + o) * 32 + 16 + w];
    }
    attn[w] = za; xs[w] = xa;
  }
  float th = theta_ry[1];
  float cb = cosf(th), sb = sinf(th);
  float m[16];
#pragma unroll
  for (int w = 0; w < 16; ++w) m[w] = cb * attn[w] - sb * xs[w];

  // x = LN(attn) * g1[1] + be1[1]
  float mu = 0.f;
#pragma unroll
  for (int w = 0; w < 16; ++w) mu += attn[w];
  mu *= (1.f / 16.f);
  float var = 0.f;
#pragma unroll
  for (int w = 0; w < 16; ++w) { float d = attn[w] - mu; var += d * d; }
  var *= (1.f / 16.f);
  float rs = rsqrtf(var + 1e-5f);
  float x[16];
#pragma unroll
  for (int w = 0; w < 16; ++w) x[w] = (attn[w] - mu) * rs * g1[16 + w] + be1[16 + w];

  // ffn = relu(m @ W1^T + b1) @ W2^T + b2   (block 1 weights)
  float ffn[16];
#pragma unroll
  for (int w = 0; w < 16; ++w) ffn[w] = b2[16 + w];
  for (int j = 0; j < 64; ++j) {
    float h = b1[64 + j];
#pragma unroll
    for (int w = 0; w < 16; ++w) h += m[w] * w1[1024 + j * 16 + w];
    h = fmaxf(h, 0.f);
#pragma unroll
    for (int w = 0; w < 16; ++w) ffn[w] += h * w2[1024 + w * 64 + j];
  }

  // feats = LN(x + ffn) * g2[1] + be2[1]
  float y[16];
#pragma unroll
  for (int w = 0; w < 16; ++w) y[w] = x[w] + ffn[w];
  float mu2 = 0.f;
#pragma unroll
  for (int w = 0; w < 16; ++w) mu2 += y[w];
  mu2 *= (1.f / 16.f);
  float var2 = 0.f;
#pragma unroll
  for (int w = 0; w < 16; ++w) { float d = y[w] - mu2; var2 += d * d; }
  var2 *= (1.f / 16.f);
  float rs2 = rsqrtf(var2 + 1e-5f);

  float ov = bh[0];
#pragma unroll
  for (int w = 0; w < 16; ++w)
    ov += ((y[w] - mu2) * rs2 * g2[16 + w] + be2[16 + w]) * wh[w];
  out[b] = ov;
}

extern "C" void kernel_launch(void* const* d_in, const int* in_sizes, int n_in,
                              void* d_out, int out_size) {
  const float* states = (const float*)d_in[0];
  const float* ra     = (const float*)d_in[1];
  const float* trx    = (const float*)d_in[2];
  const float* try_   = (const float*)d_in[3];
  const float* w1     = (const float*)d_in[4];
  const float* b1     = (const float*)d_in[5];
  const float* w2     = (const float*)d_in[6];
  const float* b2     = (const float*)d_in[7];
  const float* g1     = (const float*)d_in[8];
  const float* be1    = (const float*)d_in[9];
  const float* g2     = (const float*)d_in[10];
  const float* be2    = (const float*)d_in[11];
  const float* wh     = (const float*)d_in[12];
  const float* bh     = (const float*)d_in[13];
  float* out = (float*)d_out;

  cudaFuncSetAttribute(kP1, cudaFuncAttributeMaxDynamicSharedMemorySize, SMEM_BYTES);
  cudaFuncSetAttribute(kP2, cudaFuncAttributeMaxDynamicSharedMemorySize, SMEM_BYTES);
  cudaFuncSetAttribute(kP3, cudaFuncAttributeMaxDynamicSharedMemorySize, SMEM_BYTES);
  cudaFuncSetAttribute(kP4, cudaFuncAttributeMaxDynamicSharedMemorySize, SMEM_BYTES);
  cudaFuncSetAttribute(kP5, cudaFuncAttributeMaxDynamicSharedMemorySize, SMEM_BYTES);
  cudaFuncSetAttribute(kMeasure, cudaFuncAttributeMaxDynamicSharedMemorySize, SMEM_BYTES);

  kTrig<<<1, 32>>>(ra, trx, try_);
  kNorm<<<BSZ, 256>>>(states);
  kP1<<<BSZ * 4, NT, SMEM_BYTES>>>(states);
  kP2<<<BSZ * 4, NT, SMEM_BYTES>>>();
  kP3<<<BSZ * 4, NT, SMEM_BYTES>>>();
  kP4<<<BSZ * 4, NT, SMEM_BYTES>>>();
  kP5<<<BSZ * 4, NT, SMEM_BYTES>>>();
  kMeasure<<<BSZ * 4, NT, SMEM_BYTES>>>();
  kHead<<<(BSZ + 127) / 128, 128>>>(try_, w1, b1, w2, b2, g1, be1, g2, be2, wh, bh, out);
}